// round 1
// baseline (speedup 1.0000x reference)
#include <cuda_runtime.h>
#include <math.h>

#define NN 50000
#define NE 800000
#define FULLM 0xffffffffu

// ---------------- device scratch (static, no runtime alloc) ----------------
__device__ float d_Q[NN * 64];
__device__ float d_K[NN * 64];
__device__ float d_V[NN * 64];
__device__ float d_sbuf[NE * 64];
__device__ float d_scoreb[NE * 8];
__device__ float d_epre[NE * 64];
__device__ float d_hbuf[NN * 64];   // attention output, later reused as h1
__device__ float d_t1[NN * 64];
__device__ float d_t2[NN * 64];
__device__ float d_mid[NN * 128];
__device__ int   d_rowoff[NN + 1];
__device__ int   d_counts[NN];
__device__ int   d_cursor[NN];
__device__ int   d_col[NE];
// stats layout: [0:64) e-sum [64:128) e-sumsq [128:192) t1-sum [192:256) t1-sumsq
//               [256:320) t2-sum [320:384) t2-sumsq
__device__ float d_stats[384];

// ---------------- zero counters/stats ----------------
__global__ void k_zero() {
    int i = blockIdx.x * blockDim.x + threadIdx.x;
    if (i < NN) d_counts[i] = 0;
    if (i < 384) d_stats[i] = 0.f;
}

// ---------------- CSR build ----------------
__global__ void k_count(const int* __restrict__ eidx) {
    int e = blockIdx.x * blockDim.x + threadIdx.x;
    if (e < NE) atomicAdd(&d_counts[eidx[NE + e]], 1);
}

__global__ void k_scan() {
    __shared__ int sh[1024];
    int tid = threadIdx.x;
    const int per = (NN + 1023) / 1024;  // 49
    int s = tid * per;
    int e = s + per; if (e > NN) e = NN;
    int sum = 0;
    for (int i = s; i < e && i < NN; i++) sum += d_counts[i];
    sh[tid] = sum;
    __syncthreads();
    for (int off = 1; off < 1024; off <<= 1) {
        int t = (tid >= off) ? sh[tid - off] : 0;
        __syncthreads();
        sh[tid] += t;
        __syncthreads();
    }
    int run = sh[tid] - sum;  // exclusive prefix of this chunk
    for (int i = s; i < e && i < NN; i++) {
        d_rowoff[i] = run;
        d_cursor[i] = run;
        run += d_counts[i];
    }
    if (tid == 1023) d_rowoff[NN] = sh[1023];
}

__global__ void k_fill(const int* __restrict__ eidx) {
    int e = blockIdx.x * blockDim.x + threadIdx.x;
    if (e < NE) {
        int dst = eidx[NE + e];
        int p = atomicAdd(&d_cursor[dst], 1);
        d_col[p] = e;
    }
}

// ---------------- Q,K,V node GEMM ----------------
__global__ void __launch_bounds__(256) k_qkv(const float* __restrict__ x,
                                             const float* __restrict__ Wq,
                                             const float* __restrict__ bq,
                                             const float* __restrict__ Wk,
                                             const float* __restrict__ Wv) {
    __shared__ float sWq[4096], sWk[4096], sWv[4096];
    int tid = threadIdx.x;
    for (int i = tid; i < 4096; i += 256) { sWq[i] = Wq[i]; sWk[i] = Wk[i]; sWv[i] = Wv[i]; }
    __syncthreads();
    int l = tid & 31, w = tid >> 5;
    float bq0 = bq[l], bq1 = bq[l + 32];
    int nbase = (blockIdx.x * 8 + w) * 4;
    for (int r = 0; r < 4; r++) {
        int n = nbase + r;
        if (n >= NN) break;
        float x0 = x[n * 64 + l], x1 = x[n * 64 + 32 + l];
        float q0 = bq0, q1 = bq1, k0 = 0.f, k1 = 0.f, v0 = 0.f, v1 = 0.f;
#pragma unroll
        for (int d = 0; d < 32; d++) {
            float xv = __shfl_sync(FULLM, x0, d);
            q0 += xv * sWq[d * 64 + l]; q1 += xv * sWq[d * 64 + 32 + l];
            k0 += xv * sWk[d * 64 + l]; k1 += xv * sWk[d * 64 + 32 + l];
            v0 += xv * sWv[d * 64 + l]; v1 += xv * sWv[d * 64 + 32 + l];
        }
#pragma unroll
        for (int d = 0; d < 32; d++) {
            float xv = __shfl_sync(FULLM, x1, d);
            q0 += xv * sWq[(d + 32) * 64 + l]; q1 += xv * sWq[(d + 32) * 64 + 32 + l];
            k0 += xv * sWk[(d + 32) * 64 + l]; k1 += xv * sWk[(d + 32) * 64 + 32 + l];
            v0 += xv * sWv[(d + 32) * 64 + l]; v1 += xv * sWv[(d + 32) * 64 + 32 + l];
        }
        d_Q[n * 64 + l] = q0; d_Q[n * 64 + 32 + l] = q1;
        d_K[n * 64 + l] = k0; d_K[n * 64 + 32 + l] = k1;
        d_V[n * 64 + l] = v0; d_V[n * 64 + 32 + l] = v1;
    }
}

// ---------------- main edge kernel ----------------
// per warp: 16 edges. Computes Ee = ea@We+be, s (signed-sqrt+relu), score,
// epre = ea + s@WOe + bOe, plus BN-e stats partials.
__global__ void __launch_bounds__(256) k_edge(const float* __restrict__ ea,
                                              const int* __restrict__ eidx,
                                              const float* __restrict__ We,
                                              const float* __restrict__ be,
                                              const float* __restrict__ Aw,
                                              const float* __restrict__ WOe,
                                              const float* __restrict__ bOe) {
    __shared__ float4 sWe[2048];   // permuted: [k][lane] -> (jw0, jb0, jw1, jb1)
    __shared__ float sWOe[4096];
    int tid = threadIdx.x;
    for (int idx = tid; idx < 2048; idx += 256) {
        int k = idx >> 5, l2 = idx & 31;
        int jw = (l2 >> 3) * 16 + (l2 & 7);
        const float* row = We + k * 128;
        sWe[idx] = make_float4(row[jw], row[jw + 8], row[jw + 64], row[jw + 72]);
    }
    for (int idx = tid; idx < 4096; idx += 256) sWOe[idx] = WOe[idx];
    __syncthreads();

    int l = tid & 31, w = tid >> 5;
    int h0 = l >> 3, c0 = l & 7;
    int jw0 = h0 * 16 + c0;
    float bew0 = be[jw0], beb0 = be[jw0 + 8], bew1 = be[jw0 + 64], beb1 = be[jw0 + 72];
    float awA = Aw[c0 * 8 + h0];
    float awB = Aw[c0 * 8 + h0 + 4];
    float bo0 = bOe[l], bo1 = bOe[l + 32];
    float sum0 = 0.f, sum1 = 0.f, sq0 = 0.f, sq1 = 0.f;

    int ebase = (blockIdx.x * 8 + w) * 16;
    for (int t = 0; t < 16; t++) {
        int e = ebase + t;
        if (e >= NE) break;
        int src = eidx[e], dst = eidx[NE + e];
        float ea0 = ea[e * 64 + l], ea1 = ea[e * 64 + 32 + l];
        float a0 = bew0, a1 = beb0, a2 = bew1, a3 = beb1;
#pragma unroll
        for (int k = 0; k < 32; k++) {
            float av = __shfl_sync(FULLM, ea0, k);
            float4 wv = sWe[k * 32 + l];
            a0 += av * wv.x; a1 += av * wv.y; a2 += av * wv.z; a3 += av * wv.w;
        }
#pragma unroll
        for (int k = 0; k < 32; k++) {
            float av = __shfl_sync(FULLM, ea1, k);
            float4 wv = sWe[(k + 32) * 32 + l];
            a0 += av * wv.x; a1 += av * wv.y; a2 += av * wv.z; a3 += av * wv.w;
        }
        float kq0 = d_K[src * 64 + l] + d_Q[dst * 64 + l];
        float kq1 = d_K[src * 64 + 32 + l] + d_Q[dst * 64 + 32 + l];
        float s0 = kq0 * a0;
        s0 = copysignf(sqrtf(fabsf(s0)), s0);
        s0 = fmaxf(s0 + a1, 0.f);
        float s1 = kq1 * a2;
        s1 = copysignf(sqrtf(fabsf(s1)), s1);
        s1 = fmaxf(s1 + a3, 0.f);
        d_sbuf[e * 64 + l] = s0;
        d_sbuf[e * 64 + 32 + l] = s1;
        // score per head
        float sc0 = s0 * awA, sc1 = s1 * awB;
#pragma unroll
        for (int m = 1; m < 8; m <<= 1) {
            sc0 += __shfl_xor_sync(FULLM, sc0, m);
            sc1 += __shfl_xor_sync(FULLM, sc1, m);
        }
        if (c0 == 0) {
            d_scoreb[e * 8 + h0] = fminf(fmaxf(sc0, -5.f), 5.f);
            d_scoreb[e * 8 + h0 + 4] = fminf(fmaxf(sc1, -5.f), 5.f);
        }
        // epre = ea + s @ WOe + bOe
        float o0 = bo0 + ea0, o1 = bo1 + ea1;
#pragma unroll
        for (int d = 0; d < 32; d++) {
            float sv = __shfl_sync(FULLM, s0, d);
            o0 += sv * sWOe[d * 64 + l];
            o1 += sv * sWOe[d * 64 + 32 + l];
        }
#pragma unroll
        for (int d = 0; d < 32; d++) {
            float sv = __shfl_sync(FULLM, s1, d);
            o0 += sv * sWOe[(d + 32) * 64 + l];
            o1 += sv * sWOe[(d + 32) * 64 + 32 + l];
        }
        d_epre[e * 64 + l] = o0;
        d_epre[e * 64 + 32 + l] = o1;
        sum0 += o0; sum1 += o1; sq0 += o0 * o0; sq1 += o1 * o1;
    }
    atomicAdd(&d_stats[l], sum0);
    atomicAdd(&d_stats[l + 32], sum1);
    atomicAdd(&d_stats[64 + l], sq0);
    atomicAdd(&d_stats[96 + l], sq1);
}

// ---------------- per-node attention gather (warp per node) ----------------
__global__ void __launch_bounds__(256) k_node(const int* __restrict__ eidx,
                                              const float* __restrict__ VeRow,
                                              const float* __restrict__ dcoef) {
    int l = threadIdx.x & 31;
    int n = blockIdx.x * 8 + (threadIdx.x >> 5);
    if (n >= NN) return;
    int start = d_rowoff[n], end = d_rowoff[n + 1];

    // pass 1: per-head max over incoming edges
    float4 mA = make_float4(-1e30f, -1e30f, -1e30f, -1e30f);
    float4 mB = mA;
    for (int j = start + l; j < end; j += 32) {
        int e = d_col[j];
        const float4* sp = (const float4*)(d_scoreb + (size_t)e * 8);
        float4 a = sp[0], b = sp[1];
        mA.x = fmaxf(mA.x, a.x); mA.y = fmaxf(mA.y, a.y);
        mA.z = fmaxf(mA.z, a.z); mA.w = fmaxf(mA.w, a.w);
        mB.x = fmaxf(mB.x, b.x); mB.y = fmaxf(mB.y, b.y);
        mB.z = fmaxf(mB.z, b.z); mB.w = fmaxf(mB.w, b.w);
    }
#pragma unroll
    for (int off = 16; off; off >>= 1) {
        mA.x = fmaxf(mA.x, __shfl_xor_sync(FULLM, mA.x, off));
        mA.y = fmaxf(mA.y, __shfl_xor_sync(FULLM, mA.y, off));
        mA.z = fmaxf(mA.z, __shfl_xor_sync(FULLM, mA.z, off));
        mA.w = fmaxf(mA.w, __shfl_xor_sync(FULLM, mA.w, off));
        mB.x = fmaxf(mB.x, __shfl_xor_sync(FULLM, mB.x, off));
        mB.y = fmaxf(mB.y, __shfl_xor_sync(FULLM, mB.y, off));
        mB.z = fmaxf(mB.z, __shfl_xor_sync(FULLM, mB.z, off));
        mB.w = fmaxf(mB.w, __shfl_xor_sync(FULLM, mB.w, off));
    }
    int h0 = l >> 3;
    float m0 = (h0 == 0) ? mA.x : (h0 == 1) ? mA.y : (h0 == 2) ? mA.z : mA.w;
    float m1 = (h0 == 0) ? mB.x : (h0 == 1) ? mB.y : (h0 == 2) ? mB.z : mB.w;

    // pass 2: accumulate
    float accV0 = 0.f, accV1 = 0.f, accR0 = 0.f, accR1 = 0.f, den0 = 0.f, den1 = 0.f;
    for (int j = start; j < end; j++) {
        int e = d_col[j];
        int src = eidx[e];
        float ex0 = __expf(d_scoreb[e * 8 + h0] - m0);
        float ex1 = __expf(d_scoreb[e * 8 + h0 + 4] - m1);
        den0 += ex0; den1 += ex1;
        accV0 += d_V[src * 64 + l] * ex0;
        accV1 += d_V[src * 64 + 32 + l] * ex1;
        accR0 += d_sbuf[(size_t)e * 64 + l] * ex0;
        accR1 += d_sbuf[(size_t)e * 64 + 32 + l] * ex1;
    }
    float inv0 = 1.f / (den0 + 1e-16f), inv1 = 1.f / (den1 + 1e-16f);
    float rv0 = accR0 * inv0, rv1 = accR1 * inv1;
    float out0 = accV0 * inv0, out1 = accV1 * inv1;

    int gbase = l & 24;
#pragma unroll
    for (int k = 0; k < 8; k++) {
        float r0 = __shfl_sync(FULLM, rv0, gbase + k);
        float r1 = __shfl_sync(FULLM, rv1, gbase + k);
        out0 += r0 * VeRow[k * 64 + l];
        out1 += r1 * VeRow[k * 64 + l + 32];
    }
    float deg = (float)(end - start);
    float ld = logf(deg + 1.f);
    out0 *= (dcoef[l * 2] + ld * dcoef[l * 2 + 1]);
    out1 *= (dcoef[(l + 32) * 2] + ld * dcoef[(l + 32) * 2 + 1]);
    d_hbuf[n * 64 + l] = out0;
    d_hbuf[n * 64 + 32 + l] = out1;
}

// ---------------- t1 = x + hbuf @ WOh + bOh, BN1h stats ----------------
__global__ void __launch_bounds__(256) k_h1(const float* __restrict__ x,
                                            const float* __restrict__ WOh,
                                            const float* __restrict__ bOh) {
    __shared__ float sW[4096];
    int tid = threadIdx.x;
    for (int i = tid; i < 4096; i += 256) sW[i] = WOh[i];
    __syncthreads();
    int l = tid & 31, w = tid >> 5;
    float b0 = bOh[l], b1 = bOh[l + 32];
    float sum0 = 0.f, sum1 = 0.f, sq0 = 0.f, sq1 = 0.f;
    int nbase = (blockIdx.x * 8 + w) * 4;
    for (int r = 0; r < 4; r++) {
        int n = nbase + r;
        if (n >= NN) break;
        float hb0 = d_hbuf[n * 64 + l], hb1 = d_hbuf[n * 64 + 32 + l];
        float a0 = b0 + x[n * 64 + l], a1 = b1 + x[n * 64 + 32 + l];
#pragma unroll
        for (int d = 0; d < 32; d++) {
            float v = __shfl_sync(FULLM, hb0, d);
            a0 += v * sW[d * 64 + l];
            a1 += v * sW[d * 64 + 32 + l];
        }
#pragma unroll
        for (int d = 0; d < 32; d++) {
            float v = __shfl_sync(FULLM, hb1, d);
            a0 += v * sW[(d + 32) * 64 + l];
            a1 += v * sW[(d + 32) * 64 + 32 + l];
        }
        d_t1[n * 64 + l] = a0;
        d_t1[n * 64 + 32 + l] = a1;
        sum0 += a0; sum1 += a1; sq0 += a0 * a0; sq1 += a1 * a1;
    }
    atomicAdd(&d_stats[128 + l], sum0);
    atomicAdd(&d_stats[160 + l], sum1);
    atomicAdd(&d_stats[192 + l], sq0);
    atomicAdd(&d_stats[224 + l], sq1);
}

// ---------------- h1 = BN(t1); mid = relu(h1@W1+b1) ----------------
__global__ void __launch_bounds__(256) k_mlp1(const float* __restrict__ g1h,
                                              const float* __restrict__ be1h,
                                              const float* __restrict__ W1,
                                              const float* __restrict__ b1v) {
    __shared__ float sW[8192];  // 64x128
    int tid = threadIdx.x;
    for (int i = tid; i < 8192; i += 256) sW[i] = W1[i];
    __syncthreads();
    int l = tid & 31, w = tid >> 5;
    float mu0 = d_stats[128 + l] / NN;
    float mu1 = d_stats[160 + l] / NN;
    float var0 = d_stats[192 + l] / NN - mu0 * mu0;
    float var1 = d_stats[224 + l] / NN - mu1 * mu1;
    float sc0 = g1h[l] * rsqrtf(var0 + 1e-5f);
    float sc1 = g1h[l + 32] * rsqrtf(var1 + 1e-5f);
    float sh0 = be1h[l] - mu0 * sc0;
    float sh1 = be1h[l + 32] - mu1 * sc1;
    float bb0 = b1v[l], bb1 = b1v[l + 32], bb2 = b1v[l + 64], bb3 = b1v[l + 96];
    int nbase = (blockIdx.x * 8 + w) * 4;
    for (int r = 0; r < 4; r++) {
        int n = nbase + r;
        if (n >= NN) break;
        float h10 = d_t1[n * 64 + l] * sc0 + sh0;
        float h11 = d_t1[n * 64 + 32 + l] * sc1 + sh1;
        d_hbuf[n * 64 + l] = h10;          // reuse hbuf as h1
        d_hbuf[n * 64 + 32 + l] = h11;
        float a0 = bb0, a1 = bb1, a2 = bb2, a3 = bb3;
#pragma unroll
        for (int d = 0; d < 32; d++) {
            float v = __shfl_sync(FULLM, h10, d);
            a0 += v * sW[d * 128 + l];
            a1 += v * sW[d * 128 + l + 32];
            a2 += v * sW[d * 128 + l + 64];
            a3 += v * sW[d * 128 + l + 96];
        }
#pragma unroll
        for (int d = 0; d < 32; d++) {
            float v = __shfl_sync(FULLM, h11, d);
            a0 += v * sW[(d + 32) * 128 + l];
            a1 += v * sW[(d + 32) * 128 + l + 32];
            a2 += v * sW[(d + 32) * 128 + l + 64];
            a3 += v * sW[(d + 32) * 128 + l + 96];
        }
        d_mid[n * 128 + l]      = fmaxf(a0, 0.f);
        d_mid[n * 128 + l + 32] = fmaxf(a1, 0.f);
        d_mid[n * 128 + l + 64] = fmaxf(a2, 0.f);
        d_mid[n * 128 + l + 96] = fmaxf(a3, 0.f);
    }
}

// ---------------- t2 = h1 + mid@W2 + b2, BN2h stats ----------------
__global__ void __launch_bounds__(256) k_mlp2(const float* __restrict__ W2,
                                              const float* __restrict__ b2v) {
    __shared__ float sW[8192];  // 128x64
    int tid = threadIdx.x;
    for (int i = tid; i < 8192; i += 256) sW[i] = W2[i];
    __syncthreads();
    int l = tid & 31, w = tid >> 5;
    float bb0 = b2v[l], bb1 = b2v[l + 32];
    float sum0 = 0.f, sum1 = 0.f, sq0 = 0.f, sq1 = 0.f;
    int nbase = (blockIdx.x * 8 + w) * 4;
    for (int r = 0; r < 4; r++) {
        int n = nbase + r;
        if (n >= NN) break;
        float m0 = d_mid[n * 128 + l];
        float m1 = d_mid[n * 128 + l + 32];
        float m2 = d_mid[n * 128 + l + 64];
        float m3 = d_mid[n * 128 + l + 96];
        float f0 = bb0, f1 = bb1;
#pragma unroll
        for (int mm = 0; mm < 32; mm++) {
            float v = __shfl_sync(FULLM, m0, mm);
            f0 += v * sW[mm * 64 + l];
            f1 += v * sW[mm * 64 + 32 + l];
        }
#pragma unroll
        for (int mm = 0; mm < 32; mm++) {
            float v = __shfl_sync(FULLM, m1, mm);
            f0 += v * sW[(mm + 32) * 64 + l];
            f1 += v * sW[(mm + 32) * 64 + 32 + l];
        }
#pragma unroll
        for (int mm = 0; mm < 32; mm++) {
            float v = __shfl_sync(FULLM, m2, mm);
            f0 += v * sW[(mm + 64) * 64 + l];
            f1 += v * sW[(mm + 64) * 64 + 32 + l];
        }
#pragma unroll
        for (int mm = 0; mm < 32; mm++) {
            float v = __shfl_sync(FULLM, m3, mm);
            f0 += v * sW[(mm + 96) * 64 + l];
            f1 += v * sW[(mm + 96) * 64 + 32 + l];
        }
        float t0 = d_hbuf[n * 64 + l] + f0;
        float t1v = d_hbuf[n * 64 + 32 + l] + f1;
        d_t2[n * 64 + l] = t0;
        d_t2[n * 64 + 32 + l] = t1v;
        sum0 += t0; sum1 += t1v; sq0 += t0 * t0; sq1 += t1v * t1v;
    }
    atomicAdd(&d_stats[256 + l], sum0);
    atomicAdd(&d_stats[288 + l], sum1);
    atomicAdd(&d_stats[320 + l], sq0);
    atomicAdd(&d_stats[352 + l], sq1);
}

// ---------------- final h output: BN(t2) ----------------
__global__ void k_hout(const float* __restrict__ g2h,
                       const float* __restrict__ b2h, float* __restrict__ out) {
    int idx0 = blockIdx.x * blockDim.x + threadIdx.x;
    int stride = gridDim.x * blockDim.x;
    int col = idx0 & 63;
    float mu = d_stats[256 + col] / NN;
    float var = d_stats[320 + col] / NN - mu * mu;
    float sc = g2h[col] * rsqrtf(var + 1e-5f);
    float sh = b2h[col] - mu * sc;
    for (int i = idx0; i < NN * 64; i += stride) out[i] = d_t2[i] * sc + sh;
}

// ---------------- final e output: BN(epre) ----------------
__global__ void k_eout(const float* __restrict__ g1e,
                       const float* __restrict__ b1e, float* __restrict__ out) {
    int idx0 = blockIdx.x * blockDim.x + threadIdx.x;
    int stride = gridDim.x * blockDim.x;
    int cg = (idx0 & 15) * 4;
    float4 sc, sh;
    {
        float mu, var, s;
        mu = d_stats[cg + 0] / NE; var = d_stats[64 + cg + 0] / NE - mu * mu;
        s = g1e[cg + 0] * rsqrtf(var + 1e-5f); sc.x = s; sh.x = b1e[cg + 0] - mu * s;
        mu = d_stats[cg + 1] / NE; var = d_stats[64 + cg + 1] / NE - mu * mu;
        s = g1e[cg + 1] * rsqrtf(var + 1e-5f); sc.y = s; sh.y = b1e[cg + 1] - mu * s;
        mu = d_stats[cg + 2] / NE; var = d_stats[64 + cg + 2] / NE - mu * mu;
        s = g1e[cg + 2] * rsqrtf(var + 1e-5f); sc.z = s; sh.z = b1e[cg + 2] - mu * s;
        mu = d_stats[cg + 3] / NE; var = d_stats[64 + cg + 3] / NE - mu * mu;
        s = g1e[cg + 3] * rsqrtf(var + 1e-5f); sc.w = s; sh.w = b1e[cg + 3] - mu * s;
    }
    const float4* in = (const float4*)d_epre;
    float4* o = (float4*)out;
    const int total = NE * 16;
    for (int i = idx0; i < total; i += stride) {
        float4 v = in[i];
        v.x = v.x * sc.x + sh.x;
        v.y = v.y * sc.y + sh.y;
        v.z = v.z * sc.z + sh.z;
        v.w = v.w * sc.w + sh.w;
        o[i] = v;
    }
}

// ---------------- launch ----------------
extern "C" void kernel_launch(void* const* d_in, const int* in_sizes, int n_in,
                              void* d_out, int out_size) {
    const float* x     = (const float*)d_in[0];
    const float* ea    = (const float*)d_in[1];
    const int*   eidx  = (const int*)d_in[2];
    const float* Wq    = (const float*)d_in[3];
    const float* bq    = (const float*)d_in[4];
    const float* Wk    = (const float*)d_in[5];
    const float* We    = (const float*)d_in[6];
    const float* be    = (const float*)d_in[7];
    const float* Wv    = (const float*)d_in[8];
    const float* Aw    = (const float*)d_in[9];
    const float* VeRow = (const float*)d_in[10];
    const float* dcoef = (const float*)d_in[11];
    const float* WOh   = (const float*)d_in[12];
    const float* bOh   = (const float*)d_in[13];
    const float* WOe   = (const float*)d_in[14];
    const float* bOe   = (const float*)d_in[15];
    const float* g1h   = (const float*)d_in[16];
    const float* b1h   = (const float*)d_in[17];
    const float* g1e   = (const float*)d_in[18];
    const float* b1e   = (const float*)d_in[19];
    const float* W1    = (const float*)d_in[20];
    const float* b1v   = (const float*)d_in[21];
    const float* W2    = (const float*)d_in[22];
    const float* b2v   = (const float*)d_in[23];
    const float* g2h   = (const float*)d_in[24];
    const float* b2h   = (const float*)d_in[25];
    float* out = (float*)d_out;

    k_zero<<<196, 256>>>();
    k_count<<<3125, 256>>>(eidx);
    k_scan<<<1, 1024>>>();
    k_fill<<<3125, 256>>>(eidx);
    k_qkv<<<1563, 256>>>(x, Wq, bq, Wk, Wv);
    k_edge<<<6250, 256>>>(ea, eidx, We, be, Aw, WOe, bOe);
    k_node<<<6250, 256>>>(eidx, VeRow, dcoef);
    k_h1<<<1563, 256>>>(x, WOh, bOh);
    k_mlp1<<<1563, 256>>>(g1h, b1h, W1, b1v);
    k_mlp2<<<1563, 256>>>(W2, b2v);
    k_hout<<<512, 256>>>(g2h, b2h, out);
    k_eout<<<4096, 256>>>(g1e, b1e, out + (size_t)NN * 64);
}

// round 2
// speedup vs baseline: 1.5535x; 1.5535x over previous
#include <cuda_runtime.h>
#include <math.h>

#define NN 50000
#define NE 800000
#define FULLM 0xffffffffu

// ---------------- device scratch ----------------
__device__ float d_Q[NN * 64];
__device__ float d_K[NN * 64];
__device__ float d_V[NN * 64];
__device__ float d_sbuf[NE * 64];
__device__ float d_scoreb[NE * 8];
__device__ float d_epre[NE * 64];
__device__ float d_hbuf[NN * 64];
__device__ float d_t1[NN * 64];
__device__ float d_t2[NN * 64];
__device__ float d_mid[NN * 128];
__device__ int   d_rowoff[NN + 1];
__device__ int   d_counts[NN];
__device__ int   d_cursor[NN];
__device__ int   d_col[NE];
__device__ float d_stats[384];

__device__ __forceinline__ unsigned cvt_tf32(float x) {
    unsigned r;
    asm("cvt.rna.tf32.f32 %0, %1;" : "=r"(r) : "f"(x));
    return r;
}

#define MMA_TF32(C, A0, A1, A2, A3, B0, B1)                                   \
    asm volatile(                                                             \
        "mma.sync.aligned.m16n8k8.row.col.f32.tf32.tf32.f32 "                 \
        "{%0,%1,%2,%3}, {%4,%5,%6,%7}, {%8,%9}, {%0,%1,%2,%3};"               \
        : "+f"(C[0]), "+f"(C[1]), "+f"(C[2]), "+f"(C[3])                      \
        : "r"(A0), "r"(A1), "r"(A2), "r"(A3), "r"(B0), "r"(B1))

// ---------------- zero ----------------
__global__ void k_zero() {
    int i = blockIdx.x * blockDim.x + threadIdx.x;
    if (i < NN) d_counts[i] = 0;
    if (i < 384) d_stats[i] = 0.f;
}

// ---------------- CSR build ----------------
__global__ void k_count(const int* __restrict__ eidx) {
    int e = blockIdx.x * blockDim.x + threadIdx.x;
    if (e < NE) atomicAdd(&d_counts[eidx[NE + e]], 1);
}

__global__ void k_scan() {
    __shared__ int sh[1024];
    int tid = threadIdx.x;
    const int per = (NN + 1023) / 1024;
    int s = tid * per;
    int e = s + per; if (e > NN) e = NN;
    int sum = 0;
    for (int i = s; i < e && i < NN; i++) sum += d_counts[i];
    sh[tid] = sum;
    __syncthreads();
    for (int off = 1; off < 1024; off <<= 1) {
        int t = (tid >= off) ? sh[tid - off] : 0;
        __syncthreads();
        sh[tid] += t;
        __syncthreads();
    }
    int run = sh[tid] - sum;
    for (int i = s; i < e && i < NN; i++) {
        d_rowoff[i] = run;
        d_cursor[i] = run;
        run += d_counts[i];
    }
    if (tid == 1023) d_rowoff[NN] = sh[1023];
}

__global__ void k_fill(const int* __restrict__ eidx) {
    int e = blockIdx.x * blockDim.x + threadIdx.x;
    if (e < NE) {
        int dst = eidx[NE + e];
        int p = atomicAdd(&d_cursor[dst], 1);
        d_col[p] = e;
    }
}

// ---------------- Q,K,V node GEMM (FFMA; small) ----------------
__global__ void __launch_bounds__(256) k_qkv(const float* __restrict__ x,
                                             const float* __restrict__ Wq,
                                             const float* __restrict__ bq,
                                             const float* __restrict__ Wk,
                                             const float* __restrict__ Wv) {
    __shared__ float sWq[4096], sWk[4096], sWv[4096];
    int tid = threadIdx.x;
    for (int i = tid; i < 4096; i += 256) { sWq[i] = Wq[i]; sWk[i] = Wk[i]; sWv[i] = Wv[i]; }
    __syncthreads();
    int l = tid & 31, w = tid >> 5;
    float bq0 = bq[l], bq1 = bq[l + 32];
    int nbase = (blockIdx.x * 8 + w) * 4;
    for (int r = 0; r < 4; r++) {
        int n = nbase + r;
        if (n >= NN) break;
        float x0 = x[n * 64 + l], x1 = x[n * 64 + 32 + l];
        float q0 = bq0, q1 = bq1, k0 = 0.f, k1 = 0.f, v0 = 0.f, v1 = 0.f;
#pragma unroll
        for (int d = 0; d < 32; d++) {
            float xv = __shfl_sync(FULLM, x0, d);
            q0 += xv * sWq[d * 64 + l]; q1 += xv * sWq[d * 64 + 32 + l];
            k0 += xv * sWk[d * 64 + l]; k1 += xv * sWk[d * 64 + 32 + l];
            v0 += xv * sWv[d * 64 + l]; v1 += xv * sWv[d * 64 + 32 + l];
        }
#pragma unroll
        for (int d = 0; d < 32; d++) {
            float xv = __shfl_sync(FULLM, x1, d);
            q0 += xv * sWq[(d + 32) * 64 + l]; q1 += xv * sWq[(d + 32) * 64 + 32 + l];
            k0 += xv * sWk[(d + 32) * 64 + l]; k1 += xv * sWk[(d + 32) * 64 + 32 + l];
            v0 += xv * sWv[(d + 32) * 64 + l]; v1 += xv * sWv[(d + 32) * 64 + 32 + l];
        }
        d_Q[n * 64 + l] = q0; d_Q[n * 64 + 32 + l] = q1;
        d_K[n * 64 + l] = k0; d_K[n * 64 + 32 + l] = k1;
        d_V[n * 64 + l] = v0; d_V[n * 64 + 32 + l] = v1;
    }
}

// ---------------- edge kernel: tf32 mma ----------------
// 128 edges per block, 8 warps, warp handles 16 edge rows.
// GEMM1: Ee = ea @ We  (128x64 @ 64x128)
// epilogue: s = relu(signedsqrt((K[src]+Q[dst])*Ew) + Eb), scores, sbuf
// GEMM2: epre = ea + bOe + s @ WOe  (128x64 @ 64x64), BN stats.
__global__ void __launch_bounds__(256) k_edge_mma(const float* __restrict__ ea,
                                                  const int* __restrict__ eidx,
                                                  const float* __restrict__ We,
                                                  const float* __restrict__ be,
                                                  const float* __restrict__ Aw,
                                                  const float* __restrict__ WOe,
                                                  const float* __restrict__ bOe) {
    extern __shared__ float smem[];
    float* sA    = smem;              // 128 x 68 (raw fp32: ea, then s)
    float* sWeT  = smem + 8704;       // 128(n) x 68(k, pair-interleaved tf32)
    float* sWOeT = smem + 17408;      // 64(n) x 68(k, pair-interleaved tf32)

    const int tid = threadIdx.x;
    const int tileBase = blockIdx.x * 128;

    // fill A (raw fp32, coalesced)
    for (int i = tid; i < 8192; i += 256) {
        int r = i >> 6, c = i & 63;
        sA[r * 68 + c] = ea[(size_t)tileBase * 64 + i];
    }
    // fill WeT: dest col kd encodes (ks, t, half): k = ks*8 + (kd&7)>>1 + 4*((kd&7)&1)
    for (int i = tid; i < 8192; i += 256) {
        int k = i >> 7, n = i & 127;
        int t7 = k & 7;
        int kd = (k & ~7) + ((t7 & 3) << 1) + (t7 >> 2);
        sWeT[n * 68 + kd] = __uint_as_float(cvt_tf32(We[i]));
    }
    for (int i = tid; i < 4096; i += 256) {
        int k = i >> 6, n = i & 63;
        int t7 = k & 7;
        int kd = (k & ~7) + ((t7 & 3) << 1) + (t7 >> 2);
        sWOeT[n * 68 + kd] = __uint_as_float(cvt_tf32(WOe[i]));
    }
    __syncthreads();

    const int l = tid & 31;
    const int w16 = (tid >> 5) * 16;
    const int g = l >> 2, tig = l & 3;
    const int rowA0 = (w16 + g) * 68;
    const int rowA1 = rowA0 + 8 * 68;

    // ---- GEMM1 ----
    float c1[16][4];
#pragma unroll
    for (int nt = 0; nt < 16; nt++)
#pragma unroll
        for (int s = 0; s < 4; s++) c1[nt][s] = 0.f;

#pragma unroll
    for (int ks = 0; ks < 8; ks++) {
        unsigned a0 = cvt_tf32(sA[rowA0 + ks * 8 + tig]);
        unsigned a1 = cvt_tf32(sA[rowA1 + ks * 8 + tig]);
        unsigned a2 = cvt_tf32(sA[rowA0 + ks * 8 + tig + 4]);
        unsigned a3 = cvt_tf32(sA[rowA1 + ks * 8 + tig + 4]);
#pragma unroll
        for (int nt = 0; nt < 16; nt++) {
            float2 bb = *(const float2*)&sWeT[(nt * 8 + g) * 68 + ks * 8 + 2 * tig];
            MMA_TF32(c1[nt], a0, a1, a2, a3, __float_as_uint(bb.x), __float_as_uint(bb.y));
        }
    }

    // ---- init C2 with ea + bOe (reads sA BEFORE it is overwritten with s) ----
    float c2[8][4];
#pragma unroll
    for (int nt = 0; nt < 8; nt++) {
        int col = nt * 8 + 2 * tig;
        float2 e0v = *(const float2*)&sA[rowA0 + col];
        float2 e1v = *(const float2*)&sA[rowA1 + col];
        float bo0 = __ldg(&bOe[col]), bo1 = __ldg(&bOe[col + 1]);
        c2[nt][0] = e0v.x + bo0; c2[nt][1] = e0v.y + bo1;
        c2[nt][2] = e1v.x + bo0; c2[nt][3] = e1v.y + bo1;
    }
    __syncwarp();

    // ---- epilogue 1: s, sbuf, scores ----
    const int e0 = tileBase + w16 + g;
    const int e1 = e0 + 8;
    int src0 = eidx[e0], dst0 = eidx[NE + e0];
    int src1 = eidx[e1], dst1 = eidx[NE + e1];
    const float* K0 = d_K + (size_t)src0 * 64;
    const float* Q0 = d_Q + (size_t)dst0 * 64;
    const float* K1 = d_K + (size_t)src1 * 64;
    const float* Q1 = d_Q + (size_t)dst1 * 64;

#pragma unroll
    for (int h = 0; h < 8; h++) {
        const int nt = 2 * h;
        const int dc = h * 8 + 2 * tig;
        float2 ka = *(const float2*)(K0 + dc);
        float2 qa = *(const float2*)(Q0 + dc);
        float2 kb = *(const float2*)(K1 + dc);
        float2 qb = *(const float2*)(Q1 + dc);
        float kq00 = ka.x + qa.x, kq01 = ka.y + qa.y;
        float kq10 = kb.x + qb.x, kq11 = kb.y + qb.y;
        float bw0 = __ldg(&be[h * 16 + 2 * tig]);
        float bw1 = __ldg(&be[h * 16 + 2 * tig + 1]);
        float bb0 = __ldg(&be[h * 16 + 8 + 2 * tig]);
        float bb1 = __ldg(&be[h * 16 + 9 + 2 * tig]);
        float aw0 = __ldg(&Aw[(2 * tig) * 8 + h]);
        float aw1 = __ldg(&Aw[(2 * tig + 1) * 8 + h]);

        float t00 = kq00 * (c1[nt][0] + bw0);
        float t01 = kq01 * (c1[nt][1] + bw1);
        float t10 = kq10 * (c1[nt][2] + bw0);
        float t11 = kq11 * (c1[nt][3] + bw1);
        float s00 = fmaxf(copysignf(sqrtf(fabsf(t00)), t00) + (c1[nt + 1][0] + bb0), 0.f);
        float s01 = fmaxf(copysignf(sqrtf(fabsf(t01)), t01) + (c1[nt + 1][1] + bb1), 0.f);
        float s10 = fmaxf(copysignf(sqrtf(fabsf(t10)), t10) + (c1[nt + 1][2] + bb0), 0.f);
        float s11 = fmaxf(copysignf(sqrtf(fabsf(t11)), t11) + (c1[nt + 1][3] + bb1), 0.f);

        *(float2*)&d_sbuf[(size_t)e0 * 64 + dc] = make_float2(s00, s01);
        *(float2*)&d_sbuf[(size_t)e1 * 64 + dc] = make_float2(s10, s11);
        *(float2*)&sA[rowA0 + dc] = make_float2(s00, s01);
        *(float2*)&sA[rowA1 + dc] = make_float2(s10, s11);

        float p0 = s00 * aw0 + s01 * aw1;
        float p1 = s10 * aw0 + s11 * aw1;
        p0 += __shfl_xor_sync(FULLM, p0, 1);
        p0 += __shfl_xor_sync(FULLM, p0, 2);
        p1 += __shfl_xor_sync(FULLM, p1, 1);
        p1 += __shfl_xor_sync(FULLM, p1, 2);
        if (tig == 0) {
            d_scoreb[(size_t)e0 * 8 + h] = fminf(fmaxf(p0, -5.f), 5.f);
            d_scoreb[(size_t)e1 * 8 + h] = fminf(fmaxf(p1, -5.f), 5.f);
        }
    }
    __syncwarp();

    // ---- GEMM2: s @ WOe ----
#pragma unroll
    for (int ks = 0; ks < 8; ks++) {
        unsigned a0 = cvt_tf32(sA[rowA0 + ks * 8 + tig]);
        unsigned a1 = cvt_tf32(sA[rowA1 + ks * 8 + tig]);
        unsigned a2 = cvt_tf32(sA[rowA0 + ks * 8 + tig + 4]);
        unsigned a3 = cvt_tf32(sA[rowA1 + ks * 8 + tig + 4]);
#pragma unroll
        for (int nt = 0; nt < 8; nt++) {
            float2 bb = *(const float2*)&sWOeT[(nt * 8 + g) * 68 + ks * 8 + 2 * tig];
            MMA_TF32(c2[nt], a0, a1, a2, a3, __float_as_uint(bb.x), __float_as_uint(bb.y));
        }
    }

    // ---- epilogue 2: store epre + BN stats ----
#pragma unroll
    for (int nt = 0; nt < 8; nt++) {
        int col = nt * 8 + 2 * tig;
        *(float2*)&d_epre[(size_t)e0 * 64 + col] = make_float2(c2[nt][0], c2[nt][1]);
        *(float2*)&d_epre[(size_t)e1 * 64 + col] = make_float2(c2[nt][2], c2[nt][3]);
        float s0 = c2[nt][0] + c2[nt][2];
        float s1 = c2[nt][1] + c2[nt][3];
        float q0 = c2[nt][0] * c2[nt][0] + c2[nt][2] * c2[nt][2];
        float q1 = c2[nt][1] * c2[nt][1] + c2[nt][3] * c2[nt][3];
#pragma unroll
        for (int off = 4; off < 32; off <<= 1) {
            s0 += __shfl_xor_sync(FULLM, s0, off);
            s1 += __shfl_xor_sync(FULLM, s1, off);
            q0 += __shfl_xor_sync(FULLM, q0, off);
            q1 += __shfl_xor_sync(FULLM, q1, off);
        }
        if (l < 4) {
            atomicAdd(&d_stats[col], s0);
            atomicAdd(&d_stats[col + 1], s1);
            atomicAdd(&d_stats[64 + col], q0);
            atomicAdd(&d_stats[64 + col + 1], q1);
        }
    }
}

// ---------------- per-node attention gather (no max pass; scores clamped) ----
__global__ void __launch_bounds__(256) k_node(const int* __restrict__ eidx,
                                              const float* __restrict__ VeRow,
                                              const float* __restrict__ dcoef) {
    int l = threadIdx.x & 31;
    int n = blockIdx.x * 8 + (threadIdx.x >> 5);
    if (n >= NN) return;
    int start = d_rowoff[n], end = d_rowoff[n + 1];
    int h0 = l >> 3;

    float accV0 = 0.f, accV1 = 0.f, accR0 = 0.f, accR1 = 0.f, den0 = 0.f, den1 = 0.f;
    for (int j = start; j < end; j++) {
        int e = d_col[j];
        int src = eidx[e];
        float ex0 = __expf(d_scoreb[(size_t)e * 8 + h0]);
        float ex1 = __expf(d_scoreb[(size_t)e * 8 + h0 + 4]);
        den0 += ex0; den1 += ex1;
        accV0 += d_V[(size_t)src * 64 + l] * ex0;
        accV1 += d_V[(size_t)src * 64 + 32 + l] * ex1;
        accR0 += d_sbuf[(size_t)e * 64 + l] * ex0;
        accR1 += d_sbuf[(size_t)e * 64 + 32 + l] * ex1;
    }
    float inv0 = 1.f / (den0 + 1e-16f), inv1 = 1.f / (den1 + 1e-16f);
    float rv0 = accR0 * inv0, rv1 = accR1 * inv1;
    float out0 = accV0 * inv0, out1 = accV1 * inv1;

    int gbase = l & 24;
#pragma unroll
    for (int k = 0; k < 8; k++) {
        float r0 = __shfl_sync(FULLM, rv0, gbase + k);
        float r1 = __shfl_sync(FULLM, rv1, gbase + k);
        out0 += r0 * VeRow[k * 64 + l];
        out1 += r1 * VeRow[k * 64 + l + 32];
    }
    float deg = (float)(end - start);
    float ld = logf(deg + 1.f);
    out0 *= (dcoef[l * 2] + ld * dcoef[l * 2 + 1]);
    out1 *= (dcoef[(l + 32) * 2] + ld * dcoef[(l + 32) * 2 + 1]);
    d_hbuf[n * 64 + l] = out0;
    d_hbuf[n * 64 + 32 + l] = out1;
}

// ---------------- t1 = x + hbuf @ WOh + bOh, BN1h stats ----------------
__global__ void __launch_bounds__(256) k_h1(const float* __restrict__ x,
                                            const float* __restrict__ WOh,
                                            const float* __restrict__ bOh) {
    __shared__ float sW[4096];
    int tid = threadIdx.x;
    for (int i = tid; i < 4096; i += 256) sW[i] = WOh[i];
    __syncthreads();
    int l = tid & 31, w = tid >> 5;
    float b0 = bOh[l], b1 = bOh[l + 32];
    float sum0 = 0.f, sum1 = 0.f, sq0 = 0.f, sq1 = 0.f;
    int nbase = (blockIdx.x * 8 + w) * 4;
    for (int r = 0; r < 4; r++) {
        int n = nbase + r;
        if (n >= NN) break;
        float hb0 = d_hbuf[n * 64 + l], hb1 = d_hbuf[n * 64 + 32 + l];
        float a0 = b0 + x[n * 64 + l], a1 = b1 + x[n * 64 + 32 + l];
#pragma unroll
        for (int d = 0; d < 32; d++) {
            float v = __shfl_sync(FULLM, hb0, d);
            a0 += v * sW[d * 64 + l];
            a1 += v * sW[d * 64 + 32 + l];
        }
#pragma unroll
        for (int d = 0; d < 32; d++) {
            float v = __shfl_sync(FULLM, hb1, d);
            a0 += v * sW[(d + 32) * 64 + l];
            a1 += v * sW[(d + 32) * 64 + 32 + l];
        }
        d_t1[n * 64 + l] = a0;
        d_t1[n * 64 + 32 + l] = a1;
        sum0 += a0; sum1 += a1; sq0 += a0 * a0; sq1 += a1 * a1;
    }
    atomicAdd(&d_stats[128 + l], sum0);
    atomicAdd(&d_stats[160 + l], sum1);
    atomicAdd(&d_stats[192 + l], sq0);
    atomicAdd(&d_stats[224 + l], sq1);
}

// ---------------- h1 = BN(t1); mid = relu(h1@W1+b1) ----------------
__global__ void __launch_bounds__(256) k_mlp1(const float* __restrict__ g1h,
                                              const float* __restrict__ be1h,
                                              const float* __restrict__ W1,
                                              const float* __restrict__ b1v) {
    __shared__ float sW[8192];
    int tid = threadIdx.x;
    for (int i = tid; i < 8192; i += 256) sW[i] = W1[i];
    __syncthreads();
    int l = tid & 31, w = tid >> 5;
    float mu0 = d_stats[128 + l] / NN;
    float mu1 = d_stats[160 + l] / NN;
    float var0 = d_stats[192 + l] / NN - mu0 * mu0;
    float var1 = d_stats[224 + l] / NN - mu1 * mu1;
    float sc0 = g1h[l] * rsqrtf(var0 + 1e-5f);
    float sc1 = g1h[l + 32] * rsqrtf(var1 + 1e-5f);
    float sh0 = be1h[l] - mu0 * sc0;
    float sh1 = be1h[l + 32] - mu1 * sc1;
    float bb0 = b1v[l], bb1 = b1v[l + 32], bb2 = b1v[l + 64], bb3 = b1v[l + 96];
    int nbase = (blockIdx.x * 8 + w) * 4;
    for (int r = 0; r < 4; r++) {
        int n = nbase + r;
        if (n >= NN) break;
        float h10 = d_t1[n * 64 + l] * sc0 + sh0;
        float h11 = d_t1[n * 64 + 32 + l] * sc1 + sh1;
        d_hbuf[n * 64 + l] = h10;
        d_hbuf[n * 64 + 32 + l] = h11;
        float a0 = bb0, a1 = bb1, a2 = bb2, a3 = bb3;
#pragma unroll
        for (int d = 0; d < 32; d++) {
            float v = __shfl_sync(FULLM, h10, d);
            a0 += v * sW[d * 128 + l];
            a1 += v * sW[d * 128 + l + 32];
            a2 += v * sW[d * 128 + l + 64];
            a3 += v * sW[d * 128 + l + 96];
        }
#pragma unroll
        for (int d = 0; d < 32; d++) {
            float v = __shfl_sync(FULLM, h11, d);
            a0 += v * sW[(d + 32) * 128 + l];
            a1 += v * sW[(d + 32) * 128 + l + 32];
            a2 += v * sW[(d + 32) * 128 + l + 64];
            a3 += v * sW[(d + 32) * 128 + l + 96];
        }
        d_mid[n * 128 + l]      = fmaxf(a0, 0.f);
        d_mid[n * 128 + l + 32] = fmaxf(a1, 0.f);
        d_mid[n * 128 + l + 64] = fmaxf(a2, 0.f);
        d_mid[n * 128 + l + 96] = fmaxf(a3, 0.f);
    }
}

// ---------------- t2 = h1 + mid@W2 + b2, BN2h stats ----------------
__global__ void __launch_bounds__(256) k_mlp2(const float* __restrict__ W2,
                                              const float* __restrict__ b2v) {
    __shared__ float sW[8192];
    int tid = threadIdx.x;
    for (int i = tid; i < 8192; i += 256) sW[i] = W2[i];
    __syncthreads();
    int l = tid & 31, w = tid >> 5;
    float bb0 = b2v[l], bb1 = b2v[l + 32];
    float sum0 = 0.f, sum1 = 0.f, sq0 = 0.f, sq1 = 0.f;
    int nbase = (blockIdx.x * 8 + w) * 4;
    for (int r = 0; r < 4; r++) {
        int n = nbase + r;
        if (n >= NN) break;
        float m0 = d_mid[n * 128 + l];
        float m1 = d_mid[n * 128 + l + 32];
        float m2 = d_mid[n * 128 + l + 64];
        float m3 = d_mid[n * 128 + l + 96];
        float f0 = bb0, f1 = bb1;
#pragma unroll
        for (int mm = 0; mm < 32; mm++) {
            float v = __shfl_sync(FULLM, m0, mm);
            f0 += v * sW[mm * 64 + l];
            f1 += v * sW[mm * 64 + 32 + l];
        }
#pragma unroll
        for (int mm = 0; mm < 32; mm++) {
            float v = __shfl_sync(FULLM, m1, mm);
            f0 += v * sW[(mm + 32) * 64 + l];
            f1 += v * sW[(mm + 32) * 64 + 32 + l];
        }
#pragma unroll
        for (int mm = 0; mm < 32; mm++) {
            float v = __shfl_sync(FULLM, m2, mm);
            f0 += v * sW[(mm + 64) * 64 + l];
            f1 += v * sW[(mm + 64) * 64 + 32 + l];
        }
#pragma unroll
        for (int mm = 0; mm < 32; mm++) {
            float v = __shfl_sync(FULLM, m3, mm);
            f0 += v * sW[(mm + 96) * 64 + l];
            f1 += v * sW[(mm + 96) * 64 + 32 + l];
        }
        float t0 = d_hbuf[n * 64 + l] + f0;
        float t1v = d_hbuf[n * 64 + 32 + l] + f1;
        d_t2[n * 64 + l] = t0;
        d_t2[n * 64 + 32 + l] = t1v;
        sum0 += t0; sum1 += t1v; sq0 += t0 * t0; sq1 += t1v * t1v;
    }
    atomicAdd(&d_stats[256 + l], sum0);
    atomicAdd(&d_stats[288 + l], sum1);
    atomicAdd(&d_stats[320 + l], sq0);
    atomicAdd(&d_stats[352 + l], sq1);
}

// ---------------- final h output ----------------
__global__ void k_hout(const float* __restrict__ g2h,
                       const float* __restrict__ b2h, float* __restrict__ out) {
    int idx0 = blockIdx.x * blockDim.x + threadIdx.x;
    int stride = gridDim.x * blockDim.x;
    int col = idx0 & 63;
    float mu = d_stats[256 + col] / NN;
    float var = d_stats[320 + col] / NN - mu * mu;
    float sc = g2h[col] * rsqrtf(var + 1e-5f);
    float sh = b2h[col] - mu * sc;
    for (int i = idx0; i < NN * 64; i += stride) out[i] = d_t2[i] * sc + sh;
}

// ---------------- final e output ----------------
__global__ void k_eout(const float* __restrict__ g1e,
                       const float* __restrict__ b1e, float* __restrict__ out) {
    int idx0 = blockIdx.x * blockDim.x + threadIdx.x;
    int stride = gridDim.x * blockDim.x;
    int cg = (idx0 & 15) * 4;
    float4 sc, sh;
    {
        float mu, var, s;
        mu = d_stats[cg + 0] / NE; var = d_stats[64 + cg + 0] / NE - mu * mu;
        s = g1e[cg + 0] * rsqrtf(var + 1e-5f); sc.x = s; sh.x = b1e[cg + 0] - mu * s;
        mu = d_stats[cg + 1] / NE; var = d_stats[64 + cg + 1] / NE - mu * mu;
        s = g1e[cg + 1] * rsqrtf(var + 1e-5f); sc.y = s; sh.y = b1e[cg + 1] - mu * s;
        mu = d_stats[cg + 2] / NE; var = d_stats[64 + cg + 2] / NE - mu * mu;
        s = g1e[cg + 2] * rsqrtf(var + 1e-5f); sc.z = s; sh.z = b1e[cg + 2] - mu * s;
        mu = d_stats[cg + 3] / NE; var = d_stats[64 + cg + 3] / NE - mu * mu;
        s = g1e[cg + 3] * rsqrtf(var + 1e-5f); sc.w = s; sh.w = b1e[cg + 3] - mu * s;
    }
    const float4* in = (const float4*)d_epre;
    float4* o = (float4*)out;
    const int total = NE * 16;
    for (int i = idx0; i < total; i += stride) {
        float4 v = in[i];
        v.x = v.x * sc.x + sh.x;
        v.y = v.y * sc.y + sh.y;
        v.z = v.z * sc.z + sh.z;
        v.w = v.w * sc.w + sh.w;
        o[i] = v;
    }
}

// ---------------- launch ----------------
extern "C" void kernel_launch(void* const* d_in, const int* in_sizes, int n_in,
                              void* d_out, int out_size) {
    const float* x     = (const float*)d_in[0];
    const float* ea    = (const float*)d_in[1];
    const int*   eidx  = (const int*)d_in[2];
    const float* Wq    = (const float*)d_in[3];
    const float* bq    = (const float*)d_in[4];
    const float* Wk    = (const float*)d_in[5];
    const float* We    = (const float*)d_in[6];
    const float* be    = (const float*)d_in[7];
    const float* Wv    = (const float*)d_in[8];
    const float* Aw    = (const float*)d_in[9];
    const float* VeRow = (const float*)d_in[10];
    const float* dcoef = (const float*)d_in[11];
    const float* WOh   = (const float*)d_in[12];
    const float* bOh   = (const float*)d_in[13];
    const float* WOe   = (const float*)d_in[14];
    const float* bOe   = (const float*)d_in[15];
    const float* g1h   = (const float*)d_in[16];
    const float* b1h   = (const float*)d_in[17];
    const float* g1e   = (const float*)d_in[18];
    const float* b1e   = (const float*)d_in[19];
    const float* W1    = (const float*)d_in[20];
    const float* b1v   = (const float*)d_in[21];
    const float* W2    = (const float*)d_in[22];
    const float* b2v   = (const float*)d_in[23];
    const float* g2h   = (const float*)d_in[24];
    const float* b2h   = (const float*)d_in[25];
    float* out = (float*)d_out;

    const int edge_smem = 21760 * 4;  // 87,040 B dynamic smem
    cudaFuncSetAttribute(k_edge_mma, cudaFuncAttributeMaxDynamicSharedMemorySize, edge_smem);

    k_zero<<<196, 256>>>();
    k_count<<<3125, 256>>>(eidx);
    k_scan<<<1, 1024>>>();
    k_fill<<<3125, 256>>>(eidx);
    k_qkv<<<1563, 256>>>(x, Wq, bq, Wk, Wv);
    k_edge_mma<<<6250, 256, edge_smem>>>(ea, eidx, We, be, Aw, WOe, bOe);
    k_node<<<6250, 256>>>(eidx, VeRow, dcoef);
    k_h1<<<1563, 256>>>(x, WOh, bOh);
    k_mlp1<<<1563, 256>>>(g1h, b1h, W1, b1v);
    k_mlp2<<<1563, 256>>>(W2, b2v);
    k_hout<<<512, 256>>>(g2h, b2h, out);
    k_eout<<<4096, 256>>>(g1e, b1e, out + (size_t)NN * 64);
}